// round 2
// baseline (speedup 1.0000x reference)
#include <cuda_runtime.h>
#include <cuda_bf16.h>

// Problem constants
#define B_  2
#define S_  2048
#define HID_ 2048
#define H_  16
#define KV_ 4
#define D_  128
#define ROT_ 64
#define EMB_ 128
#define NTOK (B_ * S_)          // 4096

// ---------------- scratch (no cudaMalloc allowed) ----------------
__device__ float g_qg[(size_t)NTOK * 4096];   // hidden @ Wq  [tok][H][2D] (q | gate)
__device__ float g_kp[(size_t)NTOK * 512];    // hidden @ Wk  [tok][KV][D]
__device__ float g_vp[(size_t)NTOK * 512];    // hidden @ Wv
__device__ float g_emb[(size_t)NTOK * 128];   // hidden @ Wr
__device__ float g_q [(size_t)B_ * H_  * S_ * D_];  // [b][h][s][d] (scaled by 1/sqrt(D))
__device__ float g_k [(size_t)B_ * KV_ * S_ * D_];
__device__ float g_v [(size_t)B_ * KV_ * S_ * D_];
__device__ float g_at[(size_t)NTOK * 2048];   // attn out * sigmoid(gate), [tok][H*D]

// ---------------- SGEMM: C[M,N] = A[M,K] @ B[K,N], all row-major ----------------
// 128x128 tile, BK=16, 256 threads, 8x8 per thread (split 4+4 halves).
#define GBM 128
#define GBN 128
#define GBK 16

__global__ __launch_bounds__(256)
void sgemm_kernel(const float* __restrict__ A, const float* __restrict__ Bm,
                  float* __restrict__ C, int M, int N, int K)
{
    __shared__ float As[GBK][GBM];   // transposed A tile
    __shared__ float Bs[GBK][GBN];

    const int tid = threadIdx.x;
    const int bm = blockIdx.y * GBM;
    const int bn = blockIdx.x * GBN;
    const int rt = (tid >> 4) * 4;   // 0..60
    const int ct = (tid & 15) * 4;   // 0..60

    float acc[8][8];
#pragma unroll
    for (int i = 0; i < 8; i++)
#pragma unroll
        for (int j = 0; j < 8; j++) acc[i][j] = 0.f;

    for (int k0 = 0; k0 < K; k0 += GBK) {
#pragma unroll
        for (int t = 0; t < 2; ++t) {
            int p  = tid * 2 + t;                 // float4 id, 0..511
            int ar = p >> 2, ac = (p & 3) * 4;    // A tile: 128 rows x 16 cols
            float4 av = *(const float4*)(A + (size_t)(bm + ar) * K + k0 + ac);
            As[ac + 0][ar] = av.x; As[ac + 1][ar] = av.y;
            As[ac + 2][ar] = av.z; As[ac + 3][ar] = av.w;
            int br = p >> 5, bc = (p & 31) * 4;   // B tile: 16 rows x 128 cols
            *(float4*)&Bs[br][bc] = *(const float4*)(Bm + (size_t)(k0 + br) * N + bn + bc);
        }
        __syncthreads();
#pragma unroll
        for (int kk = 0; kk < GBK; ++kk) {
            float ra[8], rb[8];
            *(float4*)&ra[0] = *(float4*)&As[kk][rt];
            *(float4*)&ra[4] = *(float4*)&As[kk][64 + rt];
            *(float4*)&rb[0] = *(float4*)&Bs[kk][ct];
            *(float4*)&rb[4] = *(float4*)&Bs[kk][64 + ct];
#pragma unroll
            for (int i = 0; i < 8; i++)
#pragma unroll
                for (int j = 0; j < 8; j++)
                    acc[i][j] += ra[i] * rb[j];
        }
        __syncthreads();
    }
#pragma unroll
    for (int ih = 0; ih < 2; ih++)
#pragma unroll
        for (int i = 0; i < 4; i++) {
            int row = bm + ih * 64 + rt + i;
#pragma unroll
            for (int jh = 0; jh < 2; jh++) {
                float4 v = make_float4(acc[ih*4+i][jh*4+0], acc[ih*4+i][jh*4+1],
                                       acc[ih*4+i][jh*4+2], acc[ih*4+i][jh*4+3]);
                *(float4*)(C + (size_t)row * N + bn + jh * 64 + ct) = v;
            }
        }
}

// ---------------- threefry-2x32 gumbel (jax partitionable mode, key=42) ------
__device__ __forceinline__ unsigned rotl32(unsigned x, int r) {
    return (x << r) | (x >> (32 - r));
}

__device__ __forceinline__ float gumbel_noise(unsigned idx)
{
    const unsigned ks0 = 0u, ks1 = 42u;
    const unsigned ks2 = 0x1BD11BDAu ^ ks0 ^ ks1;
    unsigned x0 = 0u  + ks0;      // counts_hi = 0
    unsigned x1 = idx + ks1;      // counts_lo = idx
#define TF_RND(r) { x0 += x1; x1 = rotl32(x1, r); x1 ^= x0; }
    TF_RND(13) TF_RND(15) TF_RND(26) TF_RND(6)
    x0 += ks1; x1 += ks2 + 1u;
    TF_RND(17) TF_RND(29) TF_RND(16) TF_RND(24)
    x0 += ks2; x1 += ks0 + 2u;
    TF_RND(13) TF_RND(15) TF_RND(26) TF_RND(6)
    x0 += ks0; x1 += ks1 + 3u;
    TF_RND(17) TF_RND(29) TF_RND(16) TF_RND(24)
    x0 += ks1; x1 += ks2 + 4u;
    TF_RND(13) TF_RND(15) TF_RND(26) TF_RND(6)
    x0 += ks2; x1 += ks0 + 5u;
#undef TF_RND
    unsigned bits = x0 ^ x1;                      // 32-bit partitionable combine
    float u = __uint_as_float((bits >> 9) | 0x3f800000u) - 1.0f;  // [0,1)
    float e = -log1pf(-u);                        // Exp(1)
    return -logf(e);                              // gumbel
}

__device__ __forceinline__ float block_sum_128(float v, float* red)
{
#pragma unroll
    for (int off = 16; off; off >>= 1)
        v += __shfl_xor_sync(0xffffffffu, v, off);
    int lane = threadIdx.x & 31, w = threadIdx.x >> 5;
    if (lane == 0) red[w] = v;
    __syncthreads();
    float r = red[0] + red[1] + red[2] + red[3];
    __syncthreads();
    return r;
}

// ---------------- per-token kernel: norms, mask, rope, transpose -------------
__global__ __launch_bounds__(128)
void token_kernel(const float* __restrict__ cosT, const float* __restrict__ sinT,
                  const float* __restrict__ qnw,  const float* __restrict__ knw,
                  const float* __restrict__ Wd,   const float* __restrict__ lng,
                  const float* __restrict__ lnb,  const float* __restrict__ rnn)
{
    const int t = blockIdx.x;           // token = b*S + s
    const int d = threadIdx.x;          // 0..127
    const int b = t >> 11;
    const int s = t & (S_ - 1);

    __shared__ float sh[128];
    __shared__ float red[4];

    // ---- router: layernorm(emb) -> gelu -> @Wd -> +gumbel+BASE -> hard mask
    float e  = g_emb[(size_t)t * 128 + d] + rnn[d];
    float mu = block_sum_128(e, red) * (1.f / 128.f);
    float xc = e - mu;
    float var = block_sum_128(xc * xc, red) * (1.f / 128.f);
    float ln = xc * rsqrtf(var + 1e-5f) * lng[d] + lnb[d];
    float gl = 0.5f * ln * (1.0f + erff(ln * 0.70710678118654752f)); // exact gelu
    sh[d] = gl;
    __syncthreads();
    float logit = 0.f;
#pragma unroll 8
    for (int e2 = 0; e2 < 128; ++e2)
        logit += sh[e2] * Wd[e2 * 128 + d];
    float gum = gumbel_noise((unsigned)t * 128u + (unsigned)d);
    float maskv = ((logit + gum + 3.0f) > 0.f) ? 1.f : 0.f;
    __syncthreads();

    float cs = 0.f, sn = 0.f;
    if (d < ROT_) {
        cs = cosT[(size_t)t * ROT_ + d];
        sn = sinT[(size_t)t * ROT_ + d];
    }
    const float qscale = 0.08838834764831843f;   // 1/sqrt(128)
    const float qw = 1.f + qnw[d];
    const float kw = 1.f + knw[d];

    // ---- Q heads: rmsnorm -> mask -> rope -> [b][h][s][d] (pre-scaled)
    for (int h = 0; h < H_; ++h) {
        float x = g_qg[(size_t)t * 4096 + h * 256 + d];
        float ss = block_sum_128(x * x, red);
        float xn = x * rsqrtf(ss * (1.f / 128.f) + 1e-6f) * qw * maskv;
        sh[d] = xn;
        __syncthreads();
        float out;
        if (d < 32)       out = xn * cs - sh[d + 32] * sn;
        else if (d < 64)  out = xn * cs + sh[d - 32] * sn;
        else              out = xn;
        g_q[((size_t)(b * H_ + h) * S_ + s) * D_ + d] = out * qscale;
        __syncthreads();
    }
    // ---- K heads
    for (int kv = 0; kv < KV_; ++kv) {
        float x = g_kp[(size_t)t * 512 + kv * 128 + d];
        float ss = block_sum_128(x * x, red);
        float xn = x * rsqrtf(ss * (1.f / 128.f) + 1e-6f) * kw * maskv;
        sh[d] = xn;
        __syncthreads();
        float out;
        if (d < 32)       out = xn * cs - sh[d + 32] * sn;
        else if (d < 64)  out = xn * cs + sh[d - 32] * sn;
        else              out = xn;
        g_k[((size_t)(b * KV_ + kv) * S_ + s) * D_ + d] = out;
        __syncthreads();
        g_v[((size_t)(b * KV_ + kv) * S_ + s) * D_ + d] =
            g_vp[(size_t)t * 512 + kv * 128 + d];
    }
}

// ---------------- fused causal flash attention + gate epilogue ---------------
// BM=BN=64, D=128, 256 threads. ty=tid/16 owns rows ty+16i, tx=tid%16.
#define FBM 64
#define FBN 64
#define KPITCH 132
#define PPITCH 65

__global__ __launch_bounds__(256)
void flash_kernel(float* __restrict__ Ob)
{
    extern __shared__ float smem[];
    float (*Qs)[128]    = (float (*)[128])   smem;                 //  64*128
    float (*Ks)[KPITCH] = (float (*)[KPITCH])(smem + 64 * 128);    //  64*132
    float (*Vs)[KPITCH] = (float (*)[KPITCH])(smem + 64 * 128 + 64 * KPITCH);
    float (*Ps)[PPITCH] = (float (*)[PPITCH])(smem + 64 * 128 + 2 * 64 * KPITCH);

    const int tid = threadIdx.x;
    const int ty = tid >> 4, tx = tid & 15;
    const int qt = blockIdx.x;
    const int bh = blockIdx.y;
    const int b = bh >> 4, h = bh & 15, kv = h >> 2;
    const int qm = qt * FBM;

    const float* qp = g_q + ((size_t)(b * H_  + h ) * S_ + qm) * D_;
    const float* kp = g_k + ((size_t)(b * KV_ + kv) * S_) * D_;
    const float* vp = g_v + ((size_t)(b * KV_ + kv) * S_) * D_;

    // load Q tile (stays resident)
#pragma unroll
    for (int it = 0; it < 8; ++it) {
        int p = tid + 256 * it;
        int r = p >> 5, c4 = (p & 31) * 4;
        *(float4*)&Qs[r][c4] = *(const float4*)(qp + (size_t)r * D_ + c4);
    }

    float m_i[4], l_i[4], o[4][8];
#pragma unroll
    for (int i = 0; i < 4; i++) { m_i[i] = -1e30f; l_i[i] = 0.f; }
#pragma unroll
    for (int i = 0; i < 4; i++)
#pragma unroll
        for (int m = 0; m < 8; m++) o[i][m] = 0.f;

    const int ntiles = qt + 1;
    for (int kt = 0; kt < ntiles; ++kt) {
        const int kn = kt * FBN;
        __syncthreads();   // protects Ks/Vs reuse (and Qs visibility on kt=0)
#pragma unroll
        for (int it = 0; it < 8; ++it) {
            int p = tid + 256 * it;
            int r = p >> 5, c4 = (p & 31) * 4;
            *(float4*)&Ks[r][c4] = *(const float4*)(kp + (size_t)(kn + r) * D_ + c4);
            *(float4*)&Vs[r][c4] = *(const float4*)(vp + (size_t)(kn + r) * D_ + c4);
        }
        __syncthreads();

        // S = Q K^T (4x4 per thread)
        float sacc[4][4];
#pragma unroll
        for (int i = 0; i < 4; i++)
#pragma unroll
            for (int j = 0; j < 4; j++) sacc[i][j] = 0.f;

        for (int d4 = 0; d4 < 32; ++d4) {
            float4 qv[4], kvr[4];
#pragma unroll
            for (int i = 0; i < 4; i++) qv[i]  = *(float4*)&Qs[ty + 16 * i][d4 * 4];
#pragma unroll
            for (int j = 0; j < 4; j++) kvr[j] = *(float4*)&Ks[tx + 16 * j][d4 * 4];
#pragma unroll
            for (int i = 0; i < 4; i++)
#pragma unroll
                for (int j = 0; j < 4; j++) {
                    sacc[i][j] += qv[i].x * kvr[j].x;
                    sacc[i][j] += qv[i].y * kvr[j].y;
                    sacc[i][j] += qv[i].z * kvr[j].z;
                    sacc[i][j] += qv[i].w * kvr[j].w;
                }
        }

        const bool diag = (kn == qm);
        if (diag) {
#pragma unroll
            for (int i = 0; i < 4; i++)
#pragma unroll
                for (int j = 0; j < 4; j++)
                    if (tx + 16 * j > ty + 16 * i) sacc[i][j] = -1e30f;
        }

        // online softmax per row
#pragma unroll
        for (int i = 0; i < 4; i++) {
            float mx = sacc[i][0];
#pragma unroll
            for (int j = 1; j < 4; j++) mx = fmaxf(mx, sacc[i][j]);
#pragma unroll
            for (int off = 8; off; off >>= 1)
                mx = fmaxf(mx, __shfl_xor_sync(0xffffffffu, mx, off, 16));
            float mn = fmaxf(m_i[i], mx);
            float sc = __expf(m_i[i] - mn);
            float ls = 0.f;
#pragma unroll
            for (int j = 0; j < 4; j++) {
                float pv = __expf(sacc[i][j] - mn);
                sacc[i][j] = pv;
                ls += pv;
            }
#pragma unroll
            for (int off = 8; off; off >>= 1)
                ls += __shfl_xor_sync(0xffffffffu, ls, off, 16);
            l_i[i] = l_i[i] * sc + ls;
            m_i[i] = mn;
#pragma unroll
            for (int m = 0; m < 8; m++) o[i][m] *= sc;
#pragma unroll
            for (int j = 0; j < 4; j++)
                Ps[ty + 16 * i][tx + 16 * j] = sacc[i][j];
        }
        __syncthreads();

        // O += P V
        for (int j = 0; j < FBN; ++j) {
            float p0 = Ps[ty][j], p1 = Ps[ty + 16][j];
            float p2 = Ps[ty + 32][j], p3 = Ps[ty + 48][j];
#pragma unroll
            for (int m = 0; m < 8; m++) {
                float vv = Vs[j][tx + 16 * m];
                o[0][m] += p0 * vv; o[1][m] += p1 * vv;
                o[2][m] += p2 * vv; o[3][m] += p3 * vv;
            }
        }
    }

    // epilogue: normalize, gate, store to [tok][H*D]
#pragma unroll
    for (int i = 0; i < 4; i++) {
        float inv = 1.f / l_i[i];
        int r = qm + ty + 16 * i;
        size_t t = (size_t)b * S_ + r;
#pragma unroll
        for (int m = 0; m < 8; m++) {
            int c = tx + 16 * m;
            float gt = g_qg[t * 4096 + h * 256 + 128 + c];
            float sig = 1.f / (1.f + __expf(-gt));
            Ob[t * 2048 + h * 128 + c] = o[i][m] * inv * sig;
        }
    }
}

// ---------------- host ----------------
extern "C" void kernel_launch(void* const* d_in, const int* in_sizes, int n_in,
                              void* d_out, int out_size)
{
    const float* hidden = (const float*)d_in[0];
    const float* cosT   = (const float*)d_in[1];
    const float* sinT   = (const float*)d_in[2];
    const float* Wq     = (const float*)d_in[3];
    const float* Wk     = (const float*)d_in[4];
    const float* Wv     = (const float*)d_in[5];
    const float* Wo     = (const float*)d_in[6];
    const float* qnw    = (const float*)d_in[7];
    const float* knw    = (const float*)d_in[8];
    const float* Wr     = (const float*)d_in[9];
    const float* Wd     = (const float*)d_in[10];
    const float* lng    = (const float*)d_in[11];
    const float* lnb    = (const float*)d_in[12];
    const float* rnn    = (const float*)d_in[13];
    float* out = (float*)d_out;

    // projections (outputs land in __device__ globals referenced inside kernels)
    float* qg;  cudaGetSymbolAddress((void**)&qg,  g_qg);
    float* kp;  cudaGetSymbolAddress((void**)&kp,  g_kp);
    float* vp;  cudaGetSymbolAddress((void**)&vp,  g_vp);
    float* emb; cudaGetSymbolAddress((void**)&emb, g_emb);
    float* ab;  cudaGetSymbolAddress((void**)&ab,  g_at);

    sgemm_kernel<<<dim3(4096 / GBN, NTOK / GBM), 256>>>(hidden, Wq, qg, NTOK, 4096, HID_);
    sgemm_kernel<<<dim3(512  / GBN, NTOK / GBM), 256>>>(hidden, Wk, kp, NTOK, 512,  HID_);
    sgemm_kernel<<<dim3(512  / GBN, NTOK / GBM), 256>>>(hidden, Wv, vp, NTOK, 512,  HID_);
    sgemm_kernel<<<dim3(128  / GBN, NTOK / GBM), 256>>>(hidden, Wr, emb, NTOK, 128, HID_);

    // per-token processing
    token_kernel<<<NTOK, 128>>>(cosT, sinT, qnw, knw, Wd, lng, lnb, rnn);

    // flash attention
    const int fsmem = (64 * 128 + 2 * 64 * KPITCH + 64 * PPITCH) * (int)sizeof(float);
    cudaFuncSetAttribute(flash_kernel, cudaFuncAttributeMaxDynamicSharedMemorySize, fsmem);
    flash_kernel<<<dim3(S_ / FBM, B_ * H_), 256, fsmem>>>(ab);

    // output projection
    sgemm_kernel<<<dim3(HID_ / GBN, NTOK / GBM), 256>>>(ab, Wo, out, NTOK, HID_, HID_);
}

// round 4
// speedup vs baseline: 2.9229x; 2.9229x over previous
#include <cuda_runtime.h>
#include <cuda_bf16.h>

// Problem constants
#define B_  2
#define S_  2048
#define HID_ 2048
#define H_  16
#define KV_ 4
#define D_  128
#define ROT_ 64
#define EMB_ 128
#define NTOK (B_ * S_)          // 4096

// ---------------- scratch (no cudaMalloc allowed) ----------------
__device__ float g_qg[(size_t)NTOK * 4096];   // hidden @ Wq  [tok][H][2D] (q | gate)
__device__ float g_kp[(size_t)NTOK * 512];    // hidden @ Wk  [tok][KV][D]
__device__ float g_vp[(size_t)NTOK * 512];    // hidden @ Wv
__device__ float g_emb[(size_t)NTOK * 128];   // hidden @ Wr
__device__ float g_q [(size_t)B_ * H_  * S_ * D_];  // [b][h][s][d] (scaled by 1/sqrt(D))
__device__ float g_k [(size_t)B_ * KV_ * S_ * D_];
__device__ float g_v [(size_t)B_ * KV_ * S_ * D_];
__device__ float g_at[(size_t)NTOK * 2048];   // attn out * sigmoid(gate), [tok][H*D]

// =============== TF32 helpers ===============
__device__ __forceinline__ unsigned f2tf32(float x) {
    unsigned u;
    asm("cvt.rna.tf32.f32 %0, %1;" : "=r"(u) : "f"(x));
    return u;
}

__device__ __forceinline__ void mma_tf32(float* d, const unsigned* a, const unsigned* b) {
    asm volatile(
        "mma.sync.aligned.m16n8k8.row.col.f32.tf32.tf32.f32 "
        "{%0,%1,%2,%3}, {%4,%5,%6,%7}, {%8,%9}, {%0,%1,%2,%3};"
        : "+f"(d[0]), "+f"(d[1]), "+f"(d[2]), "+f"(d[3])
        : "r"(a[0]), "r"(a[1]), "r"(a[2]), "r"(a[3]), "r"(b[0]), "r"(b[1]));
}

// =============== TF32 tensor-core GEMM: C[M,N] = A[M,K] @ B[K,N] ===============
// Row-major A,B,C. BM=128, BN=128, BK=32, 256 threads (8 warps, 2x4), warp=64x32.
#define TBM 128
#define TBN 128
#define TBK 32
#define APITCH 36    // bank = 4g + t  -> conflict-free
#define BPITCH 136   // bank = 8t + g -> conflict-free

__global__ __launch_bounds__(256)
void tgemm_kernel(const float* __restrict__ A, const float* __restrict__ Bm,
                  float* __restrict__ C, int M, int N, int K)
{
    __shared__ unsigned As[TBM][APITCH];   // [m][k], tf32 bits
    __shared__ unsigned Bs[TBK][BPITCH];   // [k][n], tf32 bits

    const int tid  = threadIdx.x;
    const int lane = tid & 31, wid = tid >> 5;
    const int wm = (wid & 1) * 64;         // warp row offset
    const int wn = (wid >> 1) * 32;        // warp col offset
    const int g = lane >> 2, t = lane & 3;

    const int bm = blockIdx.y * TBM;
    const int bn = blockIdx.x * TBN;

    float acc[4][4][4];                    // [mt][nt][frag]
#pragma unroll
    for (int i = 0; i < 4; i++)
#pragma unroll
        for (int j = 0; j < 4; j++)
#pragma unroll
            for (int r = 0; r < 4; r++) acc[i][j][r] = 0.f;

    for (int k0 = 0; k0 < K; k0 += TBK) {
#pragma unroll
        for (int i = 0; i < 4; i++) {
            int f = tid + 256 * i;
            int r = f >> 3, c4 = (f & 7) * 4;
            float4 v = *(const float4*)(A + (size_t)(bm + r) * K + k0 + c4);
            uint4 u = make_uint4(f2tf32(v.x), f2tf32(v.y), f2tf32(v.z), f2tf32(v.w));
            *(uint4*)&As[r][c4] = u;
        }
#pragma unroll
        for (int i = 0; i < 4; i++) {
            int f = tid + 256 * i;
            int r = f >> 5, c4 = (f & 31) * 4;
            float4 v = *(const float4*)(Bm + (size_t)(k0 + r) * N + bn + c4);
            uint4 u = make_uint4(f2tf32(v.x), f2tf32(v.y), f2tf32(v.z), f2tf32(v.w));
            *(uint4*)&Bs[r][c4] = u;
        }
        __syncthreads();

#pragma unroll
        for (int kk = 0; kk < TBK / 8; ++kk) {
            unsigned af[4][4], bf[4][2];
#pragma unroll
            for (int mt = 0; mt < 4; mt++) {
                int r0 = wm + mt * 16 + g;
                int kc = kk * 8 + t;
                af[mt][0] = As[r0][kc];
                af[mt][1] = As[r0 + 8][kc];
                af[mt][2] = As[r0][kc + 4];
                af[mt][3] = As[r0 + 8][kc + 4];
            }
#pragma unroll
            for (int nt = 0; nt < 4; nt++) {
                int nc = wn + nt * 8 + g;
                bf[nt][0] = Bs[kk * 8 + t][nc];
                bf[nt][1] = Bs[kk * 8 + t + 4][nc];
            }
#pragma unroll
            for (int mt = 0; mt < 4; mt++)
#pragma unroll
                for (int nt = 0; nt < 4; nt++)
                    mma_tf32(acc[mt][nt], af[mt], bf[nt]);
        }
        __syncthreads();
    }

#pragma unroll
    for (int mt = 0; mt < 4; mt++) {
        int row = bm + wm + mt * 16 + g;
#pragma unroll
        for (int nt = 0; nt < 4; nt++) {
            int col = bn + wn + nt * 8 + 2 * t;
            *(float2*)(C + (size_t)row * N + col)       = make_float2(acc[mt][nt][0], acc[mt][nt][1]);
            *(float2*)(C + (size_t)(row + 8) * N + col) = make_float2(acc[mt][nt][2], acc[mt][nt][3]);
        }
    }
}

// ---------------- threefry-2x32 gumbel (jax partitionable mode, key=42) ------
__device__ __forceinline__ unsigned rotl32(unsigned x, int r) {
    return (x << r) | (x >> (32 - r));
}

__device__ __forceinline__ float gumbel_noise(unsigned idx)
{
    const unsigned ks0 = 0u, ks1 = 42u;
    const unsigned ks2 = 0x1BD11BDAu ^ ks0 ^ ks1;
    unsigned x0 = 0u  + ks0;
    unsigned x1 = idx + ks1;
#define TF_RND(r) { x0 += x1; x1 = rotl32(x1, r); x1 ^= x0; }
    TF_RND(13) TF_RND(15) TF_RND(26) TF_RND(6)
    x0 += ks1; x1 += ks2 + 1u;
    TF_RND(17) TF_RND(29) TF_RND(16) TF_RND(24)
    x0 += ks2; x1 += ks0 + 2u;
    TF_RND(13) TF_RND(15) TF_RND(26) TF_RND(6)
    x0 += ks0; x1 += ks1 + 3u;
    TF_RND(17) TF_RND(29) TF_RND(16) TF_RND(24)
    x0 += ks1; x1 += ks2 + 4u;
    TF_RND(13) TF_RND(15) TF_RND(26) TF_RND(6)
    x0 += ks2; x1 += ks0 + 5u;
#undef TF_RND
    unsigned bits = x0 ^ x1;
    float u = __uint_as_float((bits >> 9) | 0x3f800000u) - 1.0f;
    float e = -log1pf(-u);
    return -logf(e);
}

__device__ __forceinline__ float block_sum_128(float v, float* red)
{
#pragma unroll
    for (int off = 16; off; off >>= 1)
        v += __shfl_xor_sync(0xffffffffu, v, off);
    int lane = threadIdx.x & 31, w = threadIdx.x >> 5;
    if (lane == 0) red[w] = v;
    __syncthreads();
    float r = red[0] + red[1] + red[2] + red[3];
    __syncthreads();
    return r;
}

// ---------------- per-token kernel: norms, mask, rope, transpose -------------
__global__ __launch_bounds__(128)
void token_kernel(const float* __restrict__ cosT, const float* __restrict__ sinT,
                  const float* __restrict__ qnw,  const float* __restrict__ knw,
                  const float* __restrict__ Wd,   const float* __restrict__ lng,
                  const float* __restrict__ lnb,  const float* __restrict__ rnn)
{
    const int t = blockIdx.x;
    const int d = threadIdx.x;
    const int b = t >> 11;
    const int s = t & (S_ - 1);

    __shared__ float sh[128];
    __shared__ float red[4];

    float e  = g_emb[(size_t)t * 128 + d] + rnn[d];
    float mu = block_sum_128(e, red) * (1.f / 128.f);
    float xc = e - mu;
    float var = block_sum_128(xc * xc, red) * (1.f / 128.f);
    float ln = xc * rsqrtf(var + 1e-5f) * lng[d] + lnb[d];
    float gl = 0.5f * ln * (1.0f + erff(ln * 0.70710678118654752f));
    sh[d] = gl;
    __syncthreads();
    float logit = 0.f;
#pragma unroll 8
    for (int e2 = 0; e2 < 128; ++e2)
        logit += sh[e2] * Wd[e2 * 128 + d];
    float gum = gumbel_noise((unsigned)t * 128u + (unsigned)d);
    float maskv = ((logit + gum + 3.0f) > 0.f) ? 1.f : 0.f;
    __syncthreads();

    float cs = 0.f, sn = 0.f;
    if (d < ROT_) {
        cs = cosT[(size_t)t * ROT_ + d];
        sn = sinT[(size_t)t * ROT_ + d];
    }
    const float qscale = 0.08838834764831843f;   // 1/sqrt(128)
    const float qw = 1.f + qnw[d];
    const float kw = 1.f + knw[d];

    for (int h = 0; h < H_; ++h) {
        float x = g_qg[(size_t)t * 4096 + h * 256 + d];
        float ss = block_sum_128(x * x, red);
        float xn = x * rsqrtf(ss * (1.f / 128.f) + 1e-6f) * qw * maskv;
        sh[d] = xn;
        __syncthreads();
        float out;
        if (d < 32)       out = xn * cs - sh[d + 32] * sn;
        else if (d < 64)  out = xn * cs + sh[d - 32] * sn;
        else              out = xn;
        g_q[((size_t)(b * H_ + h) * S_ + s) * D_ + d] = out * qscale;
        __syncthreads();
    }
    for (int kv = 0; kv < KV_; ++kv) {
        float x = g_kp[(size_t)t * 512 + kv * 128 + d];
        float ss = block_sum_128(x * x, red);
        float xn = x * rsqrtf(ss * (1.f / 128.f) + 1e-6f) * kw * maskv;
        sh[d] = xn;
        __syncthreads();
        float out;
        if (d < 32)       out = xn * cs - sh[d + 32] * sn;
        else if (d < 64)  out = xn * cs + sh[d - 32] * sn;
        else              out = xn;
        g_k[((size_t)(b * KV_ + kv) * S_ + s) * D_ + d] = out;
        __syncthreads();
        g_v[((size_t)(b * KV_ + kv) * S_ + s) * D_ + d] =
            g_vp[(size_t)t * 512 + kv * 128 + d];
    }
}

// ========== TF32 tensor-core flash attention + gate epilogue ==========
// BM=128 q-rows, BN=64 keys/tile, 256 threads = 8 warps; warp w owns rows
// [w*16, w*16+16) (full 64-col strip -> softmax never crosses warps).
#define FQP 132   // Qs/Ks pitch (uints): bank = 4g+t conflict-free
#define FVP 136   // Vs pitch: bank = 8t+g conflict-free
#define FPP 68    // Ps pitch: bank = 4g+t conflict-free
#define QS_OFF 0
#define KS_OFF (128 * FQP)                 // 16896
#define VS_OFF (KS_OFF + 64 * FQP)         // 25344
#define PS_OFF (VS_OFF + 64 * FVP)         // 34048
#define FSMEM_UINTS (PS_OFF + 128 * FPP)   // 42752 -> 171008 bytes

__global__ __launch_bounds__(256)
void flashtc_kernel(float* __restrict__ Ob)
{
    extern __shared__ unsigned sm[];
    unsigned* Qs = sm + QS_OFF;
    unsigned* Ks = sm + KS_OFF;
    unsigned* Vs = sm + VS_OFF;
    unsigned* Ps = sm + PS_OFF;

    const int tid = threadIdx.x;
    const int lane = tid & 31, wid = tid >> 5;
    const int g = lane >> 2, t = lane & 3;
    const int r0 = wid * 16;

    const int bh = blockIdx.y;
    const int b = bh >> 4, h = bh & 15, kv = h >> 2;
    const int qt = gridDim.x - 1 - blockIdx.x;   // heavy blocks first
    const int qm = qt * 128;

    const float* qp = g_q + ((size_t)(b * H_  + h ) * S_ + qm) * D_;
    const float* kp = g_k + ((size_t)(b * KV_ + kv) * S_) * D_;
    const float* vp = g_v + ((size_t)(b * KV_ + kv) * S_) * D_;

    // ---- load Q tile (128x128) as tf32, resident
#pragma unroll
    for (int i = 0; i < 16; ++i) {
        int f = tid + 256 * i;
        int r = f >> 5, c4 = (f & 31) * 4;
        float4 v = *(const float4*)(qp + (size_t)r * D_ + c4);
        *(uint4*)&Qs[r * FQP + c4] =
            make_uint4(f2tf32(v.x), f2tf32(v.y), f2tf32(v.z), f2tf32(v.w));
    }

    float o[16][4];
#pragma unroll
    for (int nt = 0; nt < 16; nt++)
#pragma unroll
        for (int r = 0; r < 4; r++) o[nt][r] = 0.f;
    float m0 = -1e30f, m1 = -1e30f, l0 = 0.f, l1 = 0.f;

    const int qrow0 = qm + r0 + g;     // this thread's first row (c0/c1)
    const int qrow1 = qrow0 + 8;       // second row (c2/c3)
    const int ntiles = 2 * qt + 2;

    for (int kt = 0; kt < ntiles; ++kt) {
        const int kn = kt * 64;
        __syncthreads();   // Ks/Vs safe to overwrite (also covers Qs on kt=0)
        // ---- load K,V tiles (64x128) as tf32
#pragma unroll
        for (int i = 0; i < 8; ++i) {
            int f = tid + 256 * i;
            int r = f >> 5, c4 = (f & 31) * 4;
            float4 kvv = *(const float4*)(kp + (size_t)(kn + r) * D_ + c4);
            *(uint4*)&Ks[r * FQP + c4] =
                make_uint4(f2tf32(kvv.x), f2tf32(kvv.y), f2tf32(kvv.z), f2tf32(kvv.w));
            float4 vvv = *(const float4*)(vp + (size_t)(kn + r) * D_ + c4);
            *(uint4*)&Vs[r * FVP + c4] =
                make_uint4(f2tf32(vvv.x), f2tf32(vvv.y), f2tf32(vvv.z), f2tf32(vvv.w));
        }
        __syncthreads();

        // ---- S = Q K^T : warp m16 x n64, k=128
        float s[8][4];
#pragma unroll
        for (int nt = 0; nt < 8; nt++)
#pragma unroll
            for (int r = 0; r < 4; r++) s[nt][r] = 0.f;

#pragma unroll 4
        for (int ks = 0; ks < 16; ++ks) {
            unsigned a[4];
            a[0] = Qs[(r0 + g) * FQP + ks * 8 + t];
            a[1] = Qs[(r0 + 8 + g) * FQP + ks * 8 + t];
            a[2] = Qs[(r0 + g) * FQP + ks * 8 + t + 4];
            a[3] = Qs[(r0 + 8 + g) * FQP + ks * 8 + t + 4];
#pragma unroll
            for (int nt = 0; nt < 8; nt++) {
                unsigned bfr[2];
                bfr[0] = Ks[(nt * 8 + g) * FQP + ks * 8 + t];
                bfr[1] = Ks[(nt * 8 + g) * FQP + ks * 8 + t + 4];
                mma_tf32(s[nt], a, bfr);
            }
        }

        // ---- causal mask (only tiles crossing this warp's rows)
        if (kn + 63 > qrow0) {
#pragma unroll
            for (int nt = 0; nt < 8; nt++) {
                int c = kn + nt * 8 + 2 * t;
                if (c     > qrow0) s[nt][0] = -1e30f;
                if (c + 1 > qrow0) s[nt][1] = -1e30f;
                if (c     > qrow1) s[nt][2] = -1e30f;
                if (c + 1 > qrow1) s[nt][3] = -1e30f;
            }
        }

        // ---- online softmax (rows g and g+8; reduce across quad lanes)
        float mx0 = -1e30f, mx1 = -1e30f;
#pragma unroll
        for (int nt = 0; nt < 8; nt++) {
            mx0 = fmaxf(mx0, fmaxf(s[nt][0], s[nt][1]));
            mx1 = fmaxf(mx1, fmaxf(s[nt][2], s[nt][3]));
        }
        mx0 = fmaxf(mx0, __shfl_xor_sync(0xffffffffu, mx0, 1));
        mx0 = fmaxf(mx0, __shfl_xor_sync(0xffffffffu, mx0, 2));
        mx1 = fmaxf(mx1, __shfl_xor_sync(0xffffffffu, mx1, 1));
        mx1 = fmaxf(mx1, __shfl_xor_sync(0xffffffffu, mx1, 2));
        float mn0 = fmaxf(m0, mx0), mn1 = fmaxf(m1, mx1);
        float sc0 = __expf(m0 - mn0), sc1 = __expf(m1 - mn1);
        float ls0 = 0.f, ls1 = 0.f;
#pragma unroll
        for (int nt = 0; nt < 8; nt++) {
            float p0 = __expf(s[nt][0] - mn0);
            float p1 = __expf(s[nt][1] - mn0);
            float p2 = __expf(s[nt][2] - mn1);
            float p3 = __expf(s[nt][3] - mn1);
            ls0 += p0 + p1; ls1 += p2 + p3;
            Ps[(r0 + g) * FPP + nt * 8 + 2 * t]         = f2tf32(p0);
            Ps[(r0 + g) * FPP + nt * 8 + 2 * t + 1]     = f2tf32(p1);
            Ps[(r0 + 8 + g) * FPP + nt * 8 + 2 * t]     = f2tf32(p2);
            Ps[(r0 + 8 + g) * FPP + nt * 8 + 2 * t + 1] = f2tf32(p3);
        }
        ls0 += __shfl_xor_sync(0xffffffffu, ls0, 1);
        ls0 += __shfl_xor_sync(0xffffffffu, ls0, 2);
        ls1 += __shfl_xor_sync(0xffffffffu, ls1, 1);
        ls1 += __shfl_xor_sync(0xffffffffu, ls1, 2);
        l0 = l0 * sc0 + ls0; m0 = mn0;
        l1 = l1 * sc1 + ls1; m1 = mn1;
#pragma unroll
        for (int nt = 0; nt < 16; nt++) {
            o[nt][0] *= sc0; o[nt][1] *= sc0;
            o[nt][2] *= sc1; o[nt][3] *= sc1;
        }
        __syncwarp();   // Ps visible within warp

        // ---- O += P V : warp m16 x n128, k=64
#pragma unroll 2
        for (int ks = 0; ks < 8; ++ks) {
            unsigned a[4];
            a[0] = Ps[(r0 + g) * FPP + ks * 8 + t];
            a[1] = Ps[(r0 + 8 + g) * FPP + ks * 8 + t];
            a[2] = Ps[(r0 + g) * FPP + ks * 8 + t + 4];
            a[3] = Ps[(r0 + 8 + g) * FPP + ks * 8 + t + 4];
#pragma unroll
            for (int nt = 0; nt < 16; nt++) {
                unsigned bfr[2];
                bfr[0] = Vs[(ks * 8 + t) * FVP + nt * 8 + g];
                bfr[1] = Vs[(ks * 8 + t + 4) * FVP + nt * 8 + g];
                mma_tf32(o[nt], a, bfr);
            }
        }
        __syncwarp();   // all lanes done reading Ps before next tile rewrite
    }

    // ---- epilogue: normalize, gate, store [tok][H*D]
    float inv0 = 1.f / l0, inv1 = 1.f / l1;
    size_t t0 = (size_t)b * S_ + qrow0;
    size_t t1 = t0 + 8;
#pragma unroll
    for (int nt = 0; nt < 16; nt++) {
        int col = nt * 8 + 2 * t;
        float ga = g_qg[t0 * 4096 + h * 256 + 128 + col];
        float gb2 = g_qg[t0 * 4096 + h * 256 + 128 + col + 1];
        float gc = g_qg[t1 * 4096 + h * 256 + 128 + col];
        float gd = g_qg[t1 * 4096 + h * 256 + 128 + col + 1];
        float2 v0 = make_float2(o[nt][0] * inv0 / (1.f + __expf(-ga)),
                                o[nt][1] * inv0 / (1.f + __expf(-gb2)));
        float2 v1 = make_float2(o[nt][2] * inv1 / (1.f + __expf(-gc)),
                                o[nt][3] * inv1 / (1.f + __expf(-gd)));
        *(float2*)(Ob + t0 * 2048 + h * 128 + col) = v0;
        *(float2*)(Ob + t1 * 2048 + h * 128 + col) = v1;
    }
}

// ---------------- host ----------------
extern "C" void kernel_launch(void* const* d_in, const int* in_sizes, int n_in,
                              void* d_out, int out_size)
{
    const float* hidden = (const float*)d_in[0];
    const float* cosT   = (const float*)d_in[1];
    const float* sinT   = (const float*)d_in[2];
    const float* Wq     = (const float*)d_in[3];
    const float* Wk     = (const float*)d_in[4];
    const float* Wv     = (const float*)d_in[5];
    const float* Wo     = (const float*)d_in[6];
    const float* qnw    = (const float*)d_in[7];
    const float* knw    = (const float*)d_in[8];
    const float* Wr     = (const float*)d_in[9];
    const float* Wd     = (const float*)d_in[10];
    const float* lng    = (const float*)d_in[11];
    const float* lnb    = (const float*)d_in[12];
    const float* rnn    = (const float*)d_in[13];
    float* out = (float*)d_out;

    float* qg;  cudaGetSymbolAddress((void**)&qg,  g_qg);
    float* kp;  cudaGetSymbolAddress((void**)&kp,  g_kp);
    float* vp;  cudaGetSymbolAddress((void**)&vp,  g_vp);
    float* emb; cudaGetSymbolAddress((void**)&emb, g_emb);
    float* ab;  cudaGetSymbolAddress((void**)&ab,  g_at);

    // projections (TF32 tensor cores)
    tgemm_kernel<<<dim3(4096 / TBN, NTOK / TBM), 256>>>(hidden, Wq, qg, NTOK, 4096, HID_);
    tgemm_kernel<<<dim3(512  / TBN, NTOK / TBM), 256>>>(hidden, Wk, kp, NTOK, 512,  HID_);
    tgemm_kernel<<<dim3(512  / TBN, NTOK / TBM), 256>>>(hidden, Wv, vp, NTOK, 512,  HID_);
    tgemm_kernel<<<dim3(128  / TBN, NTOK / TBM), 256>>>(hidden, Wr, emb, NTOK, 128, HID_);

    // per-token processing
    token_kernel<<<NTOK, 128>>>(cosT, sinT, qnw, knw, Wd, lng, lnb, rnn);

    // flash attention (TF32 tensor cores)
    const int fsmem = FSMEM_UINTS * (int)sizeof(unsigned);   // 171008 B
    cudaFuncSetAttribute(flashtc_kernel, cudaFuncAttributeMaxDynamicSharedMemorySize, fsmem);
    flashtc_kernel<<<dim3(S_ / 128, B_ * H_), 256, fsmem>>>(ab);

    // output projection (TF32 tensor cores)
    tgemm_kernel<<<dim3(HID_ / TBN, NTOK / TBM), 256>>>(ab, Wo, out, NTOK, HID_, HID_);
}